// round 15
// baseline (speedup 1.0000x reference)
#include <cuda_runtime.h>
#include <cuda_fp16.h>
#include <cstdint>

// Problem constants
#define BB 2
#define CC 256
#define HH 96
#define WW 96
#define HWP (HH*WW)          // 9216
#define K9 9
#define EPSBN 1e-5f

// ---------------- scratch (device globals; no dynamic allocation) -------------
__device__ float   g_om[BB * 27 * HWP];                 // offset conv output
__device__ __half2 g_Zh[(size_t)BB * K9 * HWP * CC / 2];// Z fp16 [bk][p][o]
__device__ float   g_Zoff[(size_t)BB * K9 * HWP * 32];  // offset partials [z][p][o32]
// fp16 fragment-packed GEMM operands (m16n8k16)
__device__ uint4   g_Apkh[(size_t)BB * 576 * 16 * 32];  // [b][pb][kb16][lane]
__device__ uint2   g_Bpkh[(size_t)K9 * 32 * 16 * 32];   // [k][nb][kb16][lane]
__device__ uint2   g_Woffh[K9 * 4 * 16 * 32];           // w_off B-frags [k][nb4][kb16][lane]

// ---------------- helpers ------------------------------------------------------
__device__ __forceinline__ uint32_t smem_u32(const void* p) {
    uint32_t a;
    asm("{ .reg .u64 t; cvta.to.shared.u64 t, %1; cvt.u32.u64 %0, t; }"
        : "=r"(a) : "l"(p));
    return a;
}
__device__ __forceinline__ void cp_async16(uint32_t s, const void* g) {
    asm volatile("cp.async.cg.shared.global [%0], [%1], 16;" :: "r"(s), "l"(g));
}
__device__ __forceinline__ void cp_async8(uint32_t s, const void* g) {
    asm volatile("cp.async.ca.shared.global [%0], [%1], 8;" :: "r"(s), "l"(g));
}
#define CP_COMMIT() asm volatile("cp.async.commit_group;" ::: "memory")
#define CP_WAIT0()  asm volatile("cp.async.wait_group 0;" ::: "memory")
#define CP_WAIT1()  asm volatile("cp.async.wait_group 1;" ::: "memory")

__device__ __forceinline__ void mma_f16(float* d, const uint32_t* a, const uint32_t* b) {
    asm volatile(
        "mma.sync.aligned.m16n8k16.row.col.f32.f16.f16.f32 "
        "{%0,%1,%2,%3}, {%4,%5,%6,%7}, {%8,%9}, {%0,%1,%2,%3};"
        : "+f"(d[0]), "+f"(d[1]), "+f"(d[2]), "+f"(d[3])
        : "r"(a[0]), "r"(a[1]), "r"(a[2]), "r"(a[3]), "r"(b[0]), "r"(b[1]));
}
__device__ __forceinline__ uint32_t pack_h2(float a, float b) {
    const __half2 h = __floats2half2_rn(a, b);
    return *reinterpret_cast<const uint32_t*>(&h);
}

// =============================================================================
// pack_a_fused: x[b][c][p] -> g_Apkh fp16 A-fragments
// =============================================================================
__global__ __launch_bounds__(256) void pack_a_fused_kernel(const float* __restrict__ x)
{
    __shared__ float s[256][17];      // [c][p], pad 17
    const int b  = blockIdx.y;
    const int pb = blockIdx.x;        // 0..575
    const int p0 = pb * 16;
    const int tid = threadIdx.x;

    {
        const float4* xr = (const float4*)(x + ((size_t)b * CC + tid) * HWP + p0);
        const float4 a0 = xr[0], a1 = xr[1], a2 = xr[2], a3 = xr[3];
        s[tid][0]  = a0.x; s[tid][1]  = a0.y; s[tid][2]  = a0.z; s[tid][3]  = a0.w;
        s[tid][4]  = a1.x; s[tid][5]  = a1.y; s[tid][6]  = a1.z; s[tid][7]  = a1.w;
        s[tid][8]  = a2.x; s[tid][9]  = a2.y; s[tid][10] = a2.z; s[tid][11] = a2.w;
        s[tid][12] = a3.x; s[tid][13] = a3.y; s[tid][14] = a3.z; s[tid][15] = a3.w;
    }
    __syncthreads();

    // write fp16 m16n8k16 A-fragments
    {
        const int warp = tid >> 5, lane = tid & 31;
        const int gid = lane >> 2, qid = lane & 3;
        uint4* dstb = g_Apkh + ((size_t)b * 576 + pb) * 16 * 32;
#pragma unroll
        for (int ii = 0; ii < 2; ii++) {
            const int kb = warp * 2 + ii;
            const int c = kb * 16 + qid * 2;
            uint4 v;
            v.x = pack_h2(s[c][gid],         s[c + 1][gid]);
            v.y = pack_h2(s[c][gid + 8],     s[c + 1][gid + 8]);
            v.z = pack_h2(s[c + 8][gid],     s[c + 9][gid]);
            v.w = pack_h2(s[c + 8][gid + 8], s[c + 9][gid + 8]);
            dstb[(size_t)kb * 32 + lane] = v;
        }
    }
}

// =============================================================================
// pack_weights: w_conv -> fp16 B-frags AND w_off -> fp16 B-frags (o pad 32)
// =============================================================================
#define NWCONV (9 * 32 * 16 * 32)     // 147456
#define NWOFF  (9 * 4 * 16 * 32)      // 18432

__global__ void pack_weights_kernel(const float* __restrict__ w_conv,
                                    const float* __restrict__ w_off)
{
    const int u = blockIdx.x * blockDim.x + threadIdx.x;
    if (u < NWCONV) {
        const int k = u / (32 * 16 * 32);
        const int r = u % (32 * 16 * 32);
        const int nb = r / (16 * 32);
        const int r2 = r % (16 * 32);
        const int kb = r2 / 32;
        const int lane = r2 % 32;
        const int gid = lane >> 2, qid = lane & 3;
        const int o = nb * 8 + gid;
        const int c = kb * 16 + qid * 2;
        uint2 v;
        v.x = pack_h2(w_conv[((size_t)o * CC + c) * 9 + k],
                      w_conv[((size_t)o * CC + c + 1) * 9 + k]);
        v.y = pack_h2(w_conv[((size_t)o * CC + c + 8) * 9 + k],
                      w_conv[((size_t)o * CC + c + 9) * 9 + k]);
        g_Bpkh[u] = v;
    } else if (u < NWCONV + NWOFF) {
        const int w = u - NWCONV;          // [k][nb4][kb16][lane32]
        const int k  = w / 2048;
        const int r  = w % 2048;
        const int nb = r / 512;
        const int r2 = r % 512;
        const int kb = r2 / 32;
        const int lane = r2 % 32;
        const int gid = lane >> 2, qid = lane & 3;
        const int o = nb * 8 + gid;
        const int c = kb * 16 + qid * 2;
        uint2 v = make_uint2(0u, 0u);
        if (o < 27) {
            v.x = pack_h2(w_off[((size_t)o * CC + c) * 9 + k],
                          w_off[((size_t)o * CC + c + 1) * 9 + k]);
            v.y = pack_h2(w_off[((size_t)o * CC + c + 8) * 9 + k],
                          w_off[((size_t)o * CC + c + 9) * 9 + k]);
        }
        g_Woffh[w] = v;
    }
}

// =============================================================================
// gemm_off: Zoff[z][p][o32] = sum_c A[b][p][c] * w_off_k[o][c]
// BM=128, BN=32, BK=64; 128 thr (2x2 warps, warp tile 64x16); 3-stage pipeline
// stage = A 16KB + B 4KB = 20KB
// =============================================================================
#define GOFF_SMEM (3 * 20480)

__global__ __launch_bounds__(128, 3) void gemm_off_kernel()
{
    extern __shared__ __align__(16) char osm2[];
    const uint32_t u0 = smem_u32(osm2);

    const int tid  = threadIdx.x;
    const int warp = tid >> 5;
    const int lane = tid & 31;
    const int gid  = lane >> 2;
    const int qid  = lane & 3;
    const int wy   = warp >> 1;          // 0..1 (m)
    const int wx   = warp & 1;           // 0..1 (n)

    const int pb0 = blockIdx.x * 8;
    const int z   = blockIdx.y;
    const int b   = z / K9, k = z % K9;

    const uint4* Abase = g_Apkh + (size_t)b * 576 * 16 * 32;
    const uint2* Wbase = g_Woffh + (size_t)k * 4 * 16 * 32;

    const int akb = (tid >> 5) & 3;
    const int alane = tid & 31;

    auto load_stage = [&](int s, int kc) {
        const uint32_t sa = u0 + s * 20480;
        const uint32_t sb = sa + 16384;
#pragma unroll
        for (int it = 0; it < 8; it++) {
            cp_async16(sa + (uint32_t)(it * 128 + tid) * 16,
                       Abase + ((size_t)(pb0 + it) * 16 + kc * 4 + akb) * 32 + alane);
        }
        // B: 4 nb x 4 kb x 32 lanes = 512 uint2; 4 per thread
#pragma unroll
        for (int it = 0; it < 4; it++) {
            const int u = it * 128 + tid;          // [nb(2)][kb(2)][lane(5)]
            const int nbp = u >> 7;
            const int kbp = (u >> 5) & 3;
            cp_async8(sb + (uint32_t)u * 8,
                      Wbase + ((size_t)nbp * 16 + kc * 4 + kbp) * 32 + (u & 31));
        }
        CP_COMMIT();
    };

    float acc[4][2][4];
#pragma unroll
    for (int mt = 0; mt < 4; mt++)
#pragma unroll
        for (int nt = 0; nt < 2; nt++)
#pragma unroll
            for (int e = 0; e < 4; e++) acc[mt][nt][e] = 0.f;

    load_stage(0, 0);
    load_stage(1, 1);

#pragma unroll 1
    for (int kc = 0; kc < 4; kc++) {
        if (kc < 3) { CP_WAIT1(); } else { CP_WAIT0(); }
        __syncthreads();
        if (kc < 2) load_stage((kc + 2) % 3, kc + 2);

        char* ca = osm2 + (kc % 3) * 20480;
        char* cb = ca + 16384;

#pragma unroll
        for (int ks = 0; ks < 4; ks++) {
            uint32_t afr[4][4], bfr[2][2];
#pragma unroll
            for (int mt = 0; mt < 4; mt++) {
                const uint4 v = *(const uint4*)(ca
                    + (((wy * 4 + mt) * 4 + ks) * 32 + lane) * 16);
                afr[mt][0] = v.x; afr[mt][1] = v.y; afr[mt][2] = v.z; afr[mt][3] = v.w;
            }
#pragma unroll
            for (int nt = 0; nt < 2; nt++) {
                const uint2 v = *(const uint2*)(cb
                    + (((wx * 2 + nt) * 4 + ks) * 32 + lane) * 8);
                bfr[nt][0] = v.x; bfr[nt][1] = v.y;
            }
#pragma unroll
            for (int mt = 0; mt < 4; mt++)
#pragma unroll
                for (int nt = 0; nt < 2; nt++)
                    mma_f16(acc[mt][nt], afr[mt], bfr[nt]);
        }
    }

    // epilogue: direct fp32 stores to g_Zoff[z][p][o32]
    float* Zb = g_Zoff + (size_t)z * HWP * 32;
#pragma unroll
    for (int mt = 0; mt < 4; mt++) {
        const int row0 = pb0 * 16 + wy * 64 + mt * 16 + gid;
#pragma unroll
        for (int nt = 0; nt < 2; nt++) {
            const int col = wx * 16 + nt * 8 + qid * 2;
            float* z0 = Zb + (size_t)row0 * 32 + col;
            *(float2*)z0            = make_float2(acc[mt][nt][0], acc[mt][nt][1]);
            *(float2*)(z0 + 8 * 32) = make_float2(acc[mt][nt][2], acc[mt][nt][3]);
        }
    }
}

// =============================================================================
// offset_sum: om[b][o][p] = b_off[o] + sum_k Zoff[b*9+k][shift_k(p)][o]
// =============================================================================
__global__ __launch_bounds__(256) void offset_sum_kernel(const float* __restrict__ b_off)
{
    const int idx = blockIdx.x * 256 + threadIdx.x;   // [b][p][o32]
    if (idx >= BB * HWP * 32) return;
    const int o = idx & 31;
    const int p = (idx >> 5) % HWP;
    const int b = idx / (HWP * 32);
    if (o >= 27) return;

    const int h = p / WW, w = p - h * WW;
    float s = b_off[o];
#pragma unroll
    for (int k = 0; k < 9; k++) {
        const int hh = h + k / 3 - 1;
        const int ww = w + k % 3 - 1;
        if (hh >= 0 && hh < HH && ww >= 0 && ww < WW)
            s += g_Zoff[((size_t)(b * K9 + k) * HWP + hh * WW + ww) * 32 + o];
    }
    g_om[((size_t)b * 27 + o) * HWP + p] = s;
}

// =============================================================================
// gemm (exact R8 config): BM=128 BN=128 BK=64, 128 thr (2x2 warps, 64x64),
// 3-stage cp.async pipeline, register double-buffered fragments.
// =============================================================================
#define GEMM_SMEM 98304

__global__ __launch_bounds__(128, 2) void gemm_f16_kernel()
{
    extern __shared__ __align__(16) char gsm[];
    const uint32_t u0 = smem_u32(gsm);

    const int tid  = threadIdx.x;
    const int warp = tid >> 5;
    const int lane = tid & 31;
    const int gid  = lane >> 2;
    const int qid  = lane & 3;
    const int wy   = warp >> 1;
    const int wx   = warp & 1;

    const int pb0 = blockIdx.x * 8;
    const int nb0 = blockIdx.y * 16;
    const int z   = blockIdx.z;
    const int b   = z / K9, k = z % K9;

    const uint4* Abase = g_Apkh + (size_t)b * 576 * 16 * 32;
    const uint2* Bbase = g_Bpkh + (size_t)k * 32 * 16 * 32;

    const int akb = (tid >> 5) & 3;
    const int alane = tid & 31;
    const int bkb = (tid >> 4) & 3;
    const int bpair = tid & 15;
    const int bnbh = tid >> 6;

    auto load_stage = [&](int s, int kc) {
        const uint32_t sa = u0 + s * 32768;
        const uint32_t sb = sa + 16384;
#pragma unroll
        for (int it = 0; it < 8; it++) {
            cp_async16(sa + (uint32_t)(it * 128 + tid) * 16,
                       Abase + ((size_t)(pb0 + it) * 16 + kc * 4 + akb) * 32 + alane);
            cp_async16(sb + (uint32_t)(it * 128 + tid) * 16,
                       Bbase + ((size_t)(nb0 + it * 2 + bnbh) * 16 + kc * 4 + bkb) * 32
                             + bpair * 2);
        }
        CP_COMMIT();
    };

    float acc[4][8][4];
#pragma unroll
    for (int mt = 0; mt < 4; mt++)
#pragma unroll
        for (int nt = 0; nt < 8; nt++)
#pragma unroll
            for (int e = 0; e < 4; e++) acc[mt][nt][e] = 0.f;

    uint32_t afr[2][4][4], bfr[2][8][2];

    load_stage(0, 0);
    load_stage(1, 1);

#pragma unroll 1
    for (int kc = 0; kc < 4; kc++) {
        if (kc < 3) { CP_WAIT1(); } else { CP_WAIT0(); }
        __syncthreads();

        char* ca = gsm + (kc % 3) * 32768;
        char* cb = ca + 16384;

        // prefetch fragments for ks=0 of this stage
#pragma unroll
        for (int mt = 0; mt < 4; mt++) {
            const uint4 v = *(const uint4*)(ca + (((wy * 4 + mt) * 4) * 32 + lane) * 16);
            afr[0][mt][0] = v.x; afr[0][mt][1] = v.y;
            afr[0][mt][2] = v.z; afr[0][mt][3] = v.w;
        }
#pragma unroll
        for (int nt = 0; nt < 8; nt++) {
            const uint2 v = *(const uint2*)(cb + (((wx * 8 + nt) * 4) * 32 + lane) * 8);
            bfr[0][nt][0] = v.x; bfr[0][nt][1] = v.y;
        }

        if (kc < 2) load_stage((kc + 2) % 3, kc + 2);

#pragma unroll
        for (int ks = 0; ks < 4; ks++) {
            const int cur = ks & 1;
            if (ks < 3) {
                const int nxt = cur ^ 1;
#pragma unroll
                for (int mt = 0; mt < 4; mt++) {
                    const uint4 v = *(const uint4*)(ca
                        + (((wy * 4 + mt) * 4 + ks + 1) * 32 + lane) * 16);
                    afr[nxt][mt][0] = v.x; afr[nxt][mt][1] = v.y;
                    afr[nxt][mt][2] = v.z; afr[nxt][mt][3] = v.w;
                }
#pragma unroll
                for (int nt = 0; nt < 8; nt++) {
                    const uint2 v = *(const uint2*)(cb
                        + (((wx * 8 + nt) * 4 + ks + 1) * 32 + lane) * 8);
                    bfr[nxt][nt][0] = v.x; bfr[nxt][nt][1] = v.y;
                }
            }
#pragma unroll
            for (int mt = 0; mt < 4; mt++)
#pragma unroll
                for (int nt = 0; nt < 8; nt++)
                    mma_f16(acc[mt][nt], afr[cur][mt], bfr[cur][nt]);
        }
    }

    // epilogue: stage fp16 tile in smem (row pad 132 half2), then coalesced store
    __syncthreads();
    __half2* st = (__half2*)gsm;
#pragma unroll
    for (int mt = 0; mt < 4; mt++) {
        const int r0 = wy * 64 + mt * 16 + gid;
#pragma unroll
        for (int nt = 0; nt < 8; nt++) {
            const int n2 = wx * 32 + nt * 4 + qid;
            st[r0 * 132 + n2]       = __floats2half2_rn(acc[mt][nt][0], acc[mt][nt][1]);
            st[(r0 + 8) * 132 + n2] = __floats2half2_rn(acc[mt][nt][2], acc[mt][nt][3]);
        }
    }
    __syncthreads();

    uint4* Z4 = (uint4*)g_Zh;
#pragma unroll
    for (int it = 0; it < 16; it++) {
        const int idx = it * 128 + tid;
        const int row = idx >> 4;
        const int ch  = idx & 15;
        const uint4 v = *(const uint4*)(gsm + row * 528 + ch * 16);
        Z4[((size_t)z * HWP + pb0 * 16 + row) * 32 + nb0 + ch] = v;
    }
}

// =============================================================================
// combine (prep fused): sampling meta from g_om inline, gather Z fp16,
// BN+ReLU+residual.
// =============================================================================
__global__ __launch_bounds__(256) void combine_kernel(
    const float* __restrict__ x, const float* __restrict__ b_conv,
    const float* __restrict__ gamma, const float* __restrict__ beta,
    const float* __restrict__ run_mean, const float* __restrict__ run_var,
    float* __restrict__ out)
{
    __shared__ int   sI[32][36];
    __shared__ float sWt[32][36];
    __shared__ float sA[256], sB[256];
    __shared__ float trans[256 * 33];

    const int b  = blockIdx.y;
    const int p0 = blockIdx.x * 32;
    const int tid = threadIdx.x;

    {
        const int o = tid;
        const float inv = rsqrtf(run_var[o] + EPSBN);
        const float a = inv * gamma[o];
        sA[o] = a;
        sB[o] = (b_conv[o] - run_mean[o]) * a + beta[o];
    }

    const float* omb = g_om + (size_t)b * 27 * HWP;
    for (int i = tid; i < 32 * 9; i += 256) {
        const int px = i & 31;
        const int k  = i >> 5;
        const int p  = p0 + px;

        const float dy = omb[(2 * k) * HWP + p];
        const float dx = omb[(2 * k + 1) * HWP + p];
        const float mv = omb[(18 + k) * HWP + p];
        const float m  = 1.f / (1.f + expf(-mv));

        const int h = p / WW, w = p - h * WW;
        const float py = (float)h + (float)(k / 3 - 1) + dy;
        const float px_ = (float)w + (float)(k % 3 - 1) + dx;
        const float y0f = floorf(py), x0f = floorf(px_);
        const float ly = py - y0f, lx = px_ - x0f;
        const int y0 = (int)y0f, x0 = (int)x0f;
        const int y1 = y0 + 1,   x1 = x0 + 1;

        const bool vy0 = (y0 >= 0) & (y0 < HH);
        const bool vy1 = (y1 >= 0) & (y1 < HH);
        const bool vx0 = (x0 >= 0) & (x0 < WW);
        const bool vx1 = (x1 >= 0) & (x1 < WW);
        const int y0c = min(max(y0, 0), HH - 1), y1c = min(max(y1, 0), HH - 1);
        const int x0c = min(max(x0, 0), WW - 1), x1c = min(max(x1, 0), WW - 1);

        int4 idx;
        idx.x = y0c * WW + x0c;
        idx.y = y0c * WW + x1c;
        idx.z = y1c * WW + x0c;
        idx.w = y1c * WW + x1c;
        float4 wt;
        wt.x = (1.f - ly) * (1.f - lx) * m * ((vy0 & vx0) ? 1.f : 0.f);
        wt.y = (1.f - ly) * lx         * m * ((vy0 & vx1) ? 1.f : 0.f);
        wt.z = ly * (1.f - lx)         * m * ((vy1 & vx0) ? 1.f : 0.f);
        wt.w = ly * lx                 * m * ((vy1 & vx1) ? 1.f : 0.f);

        *(int4*)&sI[px][k * 4]    = idx;
        *(float4*)&sWt[px][k * 4] = wt;
    }
    __syncthreads();

    const int og  = tid & 7;
    const int pxl = tid >> 3;

    float acc[4][8];
#pragma unroll
    for (int t = 0; t < 4; t++)
#pragma unroll
        for (int e = 0; e < 8; e++) acc[t][e] = 0.f;

    for (int k = 0; k < K9; k++) {
        const uint4* Zk = reinterpret_cast<const uint4*>(g_Zh)
                        + ((size_t)(b * K9 + k)) * HWP * 32;
#pragma unroll
        for (int j = 0; j < 4; j++) {
            const int   idx = sI[pxl][k * 4 + j];
            const float wj  = sWt[pxl][k * 4 + j];
            const uint4* src = Zk + (size_t)idx * 32 + og;
#pragma unroll
            for (int t = 0; t < 4; t++) {
                const uint4 u = src[t * 8];
                const float2 f0 = __half22float2(*reinterpret_cast<const __half2*>(&u.x));
                const float2 f1 = __half22float2(*reinterpret_cast<const __half2*>(&u.y));
                const float2 f2 = __half22float2(*reinterpret_cast<const __half2*>(&u.z));
                const float2 f3 = __half22float2(*reinterpret_cast<const __half2*>(&u.w));
                acc[t][0] += wj * f0.x; acc[t][1] += wj * f0.y;
                acc[t][2] += wj * f1.x; acc[t][3] += wj * f1.y;
                acc[t][4] += wj * f2.x; acc[t][5] += wj * f2.y;
                acc[t][6] += wj * f3.x; acc[t][7] += wj * f3.y;
            }
        }
    }

#pragma unroll
    for (int t = 0; t < 4; t++)
#pragma unroll
        for (int e = 0; e < 8; e++) {
            const int o = t * 64 + og * 8 + e;
            trans[o * 33 + pxl] = acc[t][e];
        }
    __syncthreads();

    const float* xb = x + ((size_t)b * CC) * HWP;
    float* ob = out + ((size_t)b * CC) * HWP;
    for (int pass = 0; pass < 32; pass++) {
        const int o   = (tid >> 5) + pass * 8;
        const int pxi = tid & 31;
        float v = trans[o * 33 + pxi];
        v = fmaxf(v * sA[o] + sB[o], 0.f);
        const size_t gi = (size_t)o * HWP + p0 + pxi;
        ob[gi] = xb[gi] + v;
    }
}

// =============================================================================
extern "C" void kernel_launch(void* const* d_in, const int* in_sizes, int n_in,
                              void* d_out, int out_size)
{
    const float* x        = (const float*)d_in[0];
    const float* w_off    = (const float*)d_in[1];
    const float* b_off    = (const float*)d_in[2];
    const float* w_conv   = (const float*)d_in[3];
    const float* b_conv   = (const float*)d_in[4];
    const float* gamma    = (const float*)d_in[5];
    const float* beta     = (const float*)d_in[6];
    const float* run_mean = (const float*)d_in[7];
    const float* run_var  = (const float*)d_in[8];
    float* out = (float*)d_out;

    // lazy one-time host-side resources (no device memory)
    static cudaStream_t s1 = nullptr;
    static cudaEvent_t eFork = nullptr, eW = nullptr, eA = nullptr, eO = nullptr;
    static bool attr_done = false;
    if (!s1) {
        cudaStreamCreateWithFlags(&s1, cudaStreamNonBlocking);
        cudaEventCreateWithFlags(&eFork, cudaEventDisableTiming);
        cudaEventCreateWithFlags(&eW,    cudaEventDisableTiming);
        cudaEventCreateWithFlags(&eA,    cudaEventDisableTiming);
        cudaEventCreateWithFlags(&eO,    cudaEventDisableTiming);
    }
    if (!attr_done) {
        cudaFuncSetAttribute(gemm_f16_kernel,
                             cudaFuncAttributeMaxDynamicSharedMemorySize, GEMM_SMEM);
        cudaFuncSetAttribute(gemm_off_kernel,
                             cudaFuncAttributeMaxDynamicSharedMemorySize, GOFF_SMEM);
        attr_done = true;
    }

    cudaStream_t s0 = 0;   // origin (captured) stream

    // fork: s1 branches off s0
    cudaEventRecord(eFork, s0);
    cudaStreamWaitEvent(s1, eFork, 0);

    // s0: pack_a ; s1: pack_weights (independent)
    pack_a_fused_kernel<<<dim3(576, BB), 256, 0, s0>>>(x);
    pack_weights_kernel<<<(NWCONV + NWOFF + 255) / 256, 256, 0, s1>>>(w_conv, w_off);

    // cross dependencies: gemm (s0) needs pack_weights; gemm_off (s1) needs pack_a
    cudaEventRecord(eW, s1);
    cudaEventRecord(eA, s0);
    cudaStreamWaitEvent(s0, eW, 0);
    cudaStreamWaitEvent(s1, eA, 0);

    // s0: gemm ; s1: offset path (gemm_off -> offset_sum)
    gemm_f16_kernel<<<dim3(HWP / 128, CC / 128, BB * K9), 128, GEMM_SMEM, s0>>>();
    gemm_off_kernel<<<dim3(HWP / 128, BB * K9), 128, GOFF_SMEM, s1>>>();
    offset_sum_kernel<<<(BB * HWP * 32 + 255) / 256, 256, 0, s1>>>(b_off);

    // join: combine needs both
    cudaEventRecord(eO, s1);
    cudaStreamWaitEvent(s0, eO, 0);
    combine_kernel<<<dim3(HWP / 32, BB), 256, 0, s0>>>(x, b_conv, gamma, beta,
                                                       run_mean, run_var, out);
}

// round 16
// speedup vs baseline: 1.3162x; 1.3162x over previous
#include <cuda_runtime.h>
#include <cuda_fp16.h>
#include <cstdint>

// Problem constants
#define BB 2
#define CC 256
#define HH 96
#define WW 96
#define HWP (HH*WW)          // 9216
#define K9 9
#define EPSBN 1e-5f

// ---------------- scratch (device globals; no dynamic allocation) -------------
__device__ float   g_om[BB * 27 * HWP];                 // offset conv output
__device__ float   g_omp[4 * BB * 32 * HWP];            // per-cg partials [cg][b][o32][p]
__device__ __half2 g_Zh[(size_t)BB * K9 * HWP * CC / 2];// Z fp16 [bk][p][o]
__device__ __half  g_Axh[(size_t)BB * HWP * CC];        // fp16 x transposed [b][p][c]
// fp16 fragment-packed GEMM operands (m16n8k16)
__device__ uint4   g_Apkh[(size_t)BB * 576 * 16 * 32];  // [b][pb][kb16][lane]
__device__ uint2   g_Bpkh[(size_t)K9 * 32 * 16 * 32];   // [k][nb][kb16][lane]
__device__ uint2   g_Woffh[9 * 4 * 4 * 4 * 32];         // fp16 frag w_off [k][cg][kb][nt][lane]

// ---------------- helpers ------------------------------------------------------
__device__ __forceinline__ uint32_t smem_u32(const void* p) {
    uint32_t a;
    asm("{ .reg .u64 t; cvta.to.shared.u64 t, %1; cvt.u32.u64 %0, t; }"
        : "=r"(a) : "l"(p));
    return a;
}
__device__ __forceinline__ void cp_async16(uint32_t s, const void* g) {
    asm volatile("cp.async.cg.shared.global [%0], [%1], 16;" :: "r"(s), "l"(g));
}
#define CP_COMMIT() asm volatile("cp.async.commit_group;" ::: "memory")
#define CP_WAIT0()  asm volatile("cp.async.wait_group 0;" ::: "memory")
#define CP_WAIT1()  asm volatile("cp.async.wait_group 1;" ::: "memory")

__device__ __forceinline__ void mma_f16(float* d, const uint32_t* a, const uint32_t* b) {
    asm volatile(
        "mma.sync.aligned.m16n8k16.row.col.f32.f16.f16.f32 "
        "{%0,%1,%2,%3}, {%4,%5,%6,%7}, {%8,%9}, {%0,%1,%2,%3};"
        : "+f"(d[0]), "+f"(d[1]), "+f"(d[2]), "+f"(d[3])
        : "r"(a[0]), "r"(a[1]), "r"(a[2]), "r"(a[3]), "r"(b[0]), "r"(b[1]));
}
__device__ __forceinline__ uint32_t pack_h2(float a, float b) {
    const __half2 h = __floats2half2_rn(a, b);
    return *reinterpret_cast<const uint32_t*>(&h);
}

// =============================================================================
// pack_a_fused: x[b][c][p] -> g_Axh fp16 [b][p][c]  +  g_Apkh fp16 A-fragments
// =============================================================================
__global__ __launch_bounds__(256) void pack_a_fused_kernel(const float* __restrict__ x)
{
    __shared__ float s[256][17];      // [c][p], pad 17
    const int b  = blockIdx.y;
    const int pb = blockIdx.x;        // 0..575
    const int p0 = pb * 16;
    const int tid = threadIdx.x;

    {
        const float4* xr = (const float4*)(x + ((size_t)b * CC + tid) * HWP + p0);
        const float4 a0 = xr[0], a1 = xr[1], a2 = xr[2], a3 = xr[3];
        s[tid][0]  = a0.x; s[tid][1]  = a0.y; s[tid][2]  = a0.z; s[tid][3]  = a0.w;
        s[tid][4]  = a1.x; s[tid][5]  = a1.y; s[tid][6]  = a1.z; s[tid][7]  = a1.w;
        s[tid][8]  = a2.x; s[tid][9]  = a2.y; s[tid][10] = a2.z; s[tid][11] = a2.w;
        s[tid][12] = a3.x; s[tid][13] = a3.y; s[tid][14] = a3.z; s[tid][15] = a3.w;
    }
    __syncthreads();

    // write g_Axh[p][c] fp16 (for offset conv)
    {
        const int p  = tid >> 4;
        const int cq = tid & 15;
        uint32_t h2b[8];
#pragma unroll
        for (int j = 0; j < 8; j++)
            h2b[j] = pack_h2(s[cq * 16 + 2 * j][p], s[cq * 16 + 2 * j + 1][p]);
        uint4* dst = (uint4*)(g_Axh + ((size_t)b * HWP + p0 + p) * CC + cq * 16);
        dst[0] = make_uint4(h2b[0], h2b[1], h2b[2], h2b[3]);
        dst[1] = make_uint4(h2b[4], h2b[5], h2b[6], h2b[7]);
    }

    // write fp16 m16n8k16 A-fragments
    {
        const int warp = tid >> 5, lane = tid & 31;
        const int gid = lane >> 2, qid = lane & 3;
        uint4* dstb = g_Apkh + ((size_t)b * 576 + pb) * 16 * 32;
#pragma unroll
        for (int ii = 0; ii < 2; ii++) {
            const int kb = warp * 2 + ii;
            const int c = kb * 16 + qid * 2;
            uint4 v;
            v.x = pack_h2(s[c][gid],         s[c + 1][gid]);
            v.y = pack_h2(s[c][gid + 8],     s[c + 1][gid + 8]);
            v.z = pack_h2(s[c + 8][gid],     s[c + 9][gid]);
            v.w = pack_h2(s[c + 8][gid + 8], s[c + 9][gid + 8]);
            dstb[(size_t)kb * 32 + lane] = v;
        }
    }
}

// =============================================================================
// pack_weights: w_conv -> fp16 B-frags  AND  w_off -> fp16 frags (o pad 32)
// =============================================================================
#define NWCONV (9 * 32 * 16 * 32)     // 147456
#define NWOFF  (9 * 4 * 4 * 4 * 32)   // 18432

__global__ void pack_weights_kernel(const float* __restrict__ w_conv,
                                    const float* __restrict__ w_off)
{
    const int u = blockIdx.x * blockDim.x + threadIdx.x;
    if (u < NWCONV) {
        const int k = u / (32 * 16 * 32);
        const int r = u % (32 * 16 * 32);
        const int nb = r / (16 * 32);
        const int r2 = r % (16 * 32);
        const int kb = r2 / 32;
        const int lane = r2 % 32;
        const int gid = lane >> 2, qid = lane & 3;
        const int o = nb * 8 + gid;
        const int c = kb * 16 + qid * 2;
        uint2 v;
        v.x = pack_h2(w_conv[((size_t)o * CC + c) * 9 + k],
                      w_conv[((size_t)o * CC + c + 1) * 9 + k]);
        v.y = pack_h2(w_conv[((size_t)o * CC + c + 8) * 9 + k],
                      w_conv[((size_t)o * CC + c + 9) * 9 + k]);
        g_Bpkh[u] = v;
    } else if (u < NWCONV + NWOFF) {
        const int w = u - NWCONV;          // [k][cg][kb4][nt4][lane32]
        const int k  = w / 2048;
        const int r  = w % 2048;
        const int cg = r / 512;
        const int r2 = r % 512;
        const int kb = r2 / 128;
        const int r3 = r2 % 128;
        const int nt = r3 / 32;
        const int lane = r3 % 32;
        const int gid = lane >> 2, qid = lane & 3;
        const int o = nt * 8 + gid;
        const int c = cg * 64 + kb * 16 + qid * 2;
        uint2 v = make_uint2(0u, 0u);
        if (o < 27) {
            v.x = pack_h2(w_off[((size_t)o * CC + c) * 9 + k],
                          w_off[((size_t)o * CC + c + 1) * 9 + k]);
            v.y = pack_h2(w_off[((size_t)o * CC + c + 8) * 9 + k],
                          w_off[((size_t)o * CC + c + 9) * 9 + k]);
        }
        g_Woffh[w] = v;
    }
}

// =============================================================================
// offset_mma_cg: per-cg partial conv via fp16 MMA.
// grid (h=96, b=2, cg=4), 192 thr = 6 warps (16 x-pixels each).
// omp[cg][b][o32][p] = sum over this cg's 64 channels of conv taps.
// =============================================================================
#define OC_RS 72
#define OC_ASM_BYTES (((3 * 98 * OC_RS * 2) + 15) & ~15)
#define OC_SMEM (OC_ASM_BYTES + 9 * 512 * 8)

__global__ __launch_bounds__(192) void offset_mma_cg_kernel()
{
    extern __shared__ __align__(16) char osm[];
    __half* Asm = (__half*)osm;                       // [3][98][OC_RS]
    uint2*  Bsm = (uint2*)(osm + OC_ASM_BYTES);       // [9][512]

    const int tid = threadIdx.x;
    const int warp = tid >> 5, lane = tid & 31;
    const int gid = lane >> 2, qid = lane & 3;
    const int h = blockIdx.x, b = blockIdx.y, cg = blockIdx.z;

    // B frags for this cg, all 9 taps
    for (int t = tid; t < 9 * 512; t += 192)
        Bsm[t] = g_Woffh[(size_t)((t >> 9) * 4 + cg) * 512 + (t & 511)];
    // A halo: 3 x 98 rows x 64 fp16 channels of this cg
    for (int t = tid; t < 3 * 98 * 8; t += 192) {
        const int ky = t / (98 * 8);
        const int rr = t % (98 * 8);
        const int i = rr >> 3, j = rr & 7;
        const int hh = h + ky - 1;
        const int xx = i - 1;
        uint4 v = make_uint4(0u, 0u, 0u, 0u);
        if (hh >= 0 && hh < HH && xx >= 0 && xx < WW)
            v = *(const uint4*)(g_Axh + ((size_t)b * HWP + hh * WW + xx) * CC
                                + cg * 64 + j * 8);
        *(uint4*)&Asm[(ky * 98 + i) * OC_RS + j * 8] = v;
    }
    __syncthreads();

    float acc[4][4];
#pragma unroll
    for (int nt = 0; nt < 4; nt++)
#pragma unroll
        for (int e = 0; e < 4; e++) acc[nt][e] = 0.f;

    for (int k = 0; k < 9; k++) {
        const int ky = k / 3, kx = k % 3;
        const __half* Ab = Asm + (size_t)ky * 98 * OC_RS;
        const uint2* Bk = Bsm + k * 512;
        const int row = warp * 16 + gid + kx;
#pragma unroll
        for (int kb = 0; kb < 4; kb++) {
            const int c0 = kb * 16 + qid * 2;
            uint32_t a[4];
            a[0] = *(const uint32_t*)&Ab[row * OC_RS + c0];
            a[1] = *(const uint32_t*)&Ab[(row + 8) * OC_RS + c0];
            a[2] = *(const uint32_t*)&Ab[row * OC_RS + c0 + 8];
            a[3] = *(const uint32_t*)&Ab[(row + 8) * OC_RS + c0 + 8];
#pragma unroll
            for (int nt = 0; nt < 4; nt++) {
                const uint2 bv = Bk[(kb * 4 + nt) * 32 + lane];
                uint32_t bf[2] = { bv.x, bv.y };
                mma_f16(acc[nt], a, bf);
            }
        }
    }

    float* dstb = g_omp + ((size_t)(cg * BB + b) * 32) * HWP + h * WW;
#pragma unroll
    for (int nt = 0; nt < 4; nt++) {
#pragma unroll
        for (int e = 0; e < 4; e++) {
            const int o = nt * 8 + qid * 2 + (e & 1);
            const int xx = warp * 16 + gid + ((e >= 2) ? 8 : 0);
            if (o < 27)
                dstb[(size_t)o * HWP + xx] = acc[nt][e];
        }
    }
}

// =============================================================================
// om_sum: g_om[b][o][p] = b_off[o] + sum_cg g_omp[cg][b][o][p]
// =============================================================================
__global__ __launch_bounds__(256) void om_sum_kernel(const float* __restrict__ b_off)
{
    const int idx = blockIdx.x * 256 + threadIdx.x;
    if (idx >= BB * 27 * HWP) return;
    const int p = idx % HWP;
    const int o = (idx / HWP) % 27;
    const int b = idx / (27 * HWP);

    float s = b_off[o];
#pragma unroll
    for (int cg = 0; cg < 4; cg++)
        s += g_omp[((size_t)(cg * BB + b) * 32 + o) * HWP + p];
    g_om[((size_t)b * 27 + o) * HWP + p] = s;
}

// =============================================================================
// gemm (exact R8 config): BM=128 BN=128 BK=64, 128 thr (2x2 warps, 64x64),
// 3-stage cp.async pipeline, register double-buffered fragments.
// =============================================================================
#define GEMM_SMEM 98304

__global__ __launch_bounds__(128, 2) void gemm_f16_kernel()
{
    extern __shared__ __align__(16) char gsm[];
    const uint32_t u0 = smem_u32(gsm);

    const int tid  = threadIdx.x;
    const int warp = tid >> 5;
    const int lane = tid & 31;
    const int gid  = lane >> 2;
    const int qid  = lane & 3;
    const int wy   = warp >> 1;
    const int wx   = warp & 1;

    const int pb0 = blockIdx.x * 8;
    const int nb0 = blockIdx.y * 16;
    const int z   = blockIdx.z;
    const int b   = z / K9, k = z % K9;

    const uint4* Abase = g_Apkh + (size_t)b * 576 * 16 * 32;
    const uint2* Bbase = g_Bpkh + (size_t)k * 32 * 16 * 32;

    const int akb = (tid >> 5) & 3;
    const int alane = tid & 31;
    const int bkb = (tid >> 4) & 3;
    const int bpair = tid & 15;
    const int bnbh = tid >> 6;

    auto load_stage = [&](int s, int kc) {
        const uint32_t sa = u0 + s * 32768;
        const uint32_t sb = sa + 16384;
#pragma unroll
        for (int it = 0; it < 8; it++) {
            cp_async16(sa + (uint32_t)(it * 128 + tid) * 16,
                       Abase + ((size_t)(pb0 + it) * 16 + kc * 4 + akb) * 32 + alane);
            cp_async16(sb + (uint32_t)(it * 128 + tid) * 16,
                       Bbase + ((size_t)(nb0 + it * 2 + bnbh) * 16 + kc * 4 + bkb) * 32
                             + bpair * 2);
        }
        CP_COMMIT();
    };

    float acc[4][8][4];
#pragma unroll
    for (int mt = 0; mt < 4; mt++)
#pragma unroll
        for (int nt = 0; nt < 8; nt++)
#pragma unroll
            for (int e = 0; e < 4; e++) acc[mt][nt][e] = 0.f;

    uint32_t afr[2][4][4], bfr[2][8][2];

    load_stage(0, 0);
    load_stage(1, 1);

#pragma unroll 1
    for (int kc = 0; kc < 4; kc++) {
        if (kc < 3) { CP_WAIT1(); } else { CP_WAIT0(); }
        __syncthreads();

        char* ca = gsm + (kc % 3) * 32768;
        char* cb = ca + 16384;

        // prefetch fragments for ks=0 of this stage
#pragma unroll
        for (int mt = 0; mt < 4; mt++) {
            const uint4 v = *(const uint4*)(ca + (((wy * 4 + mt) * 4) * 32 + lane) * 16);
            afr[0][mt][0] = v.x; afr[0][mt][1] = v.y;
            afr[0][mt][2] = v.z; afr[0][mt][3] = v.w;
        }
#pragma unroll
        for (int nt = 0; nt < 8; nt++) {
            const uint2 v = *(const uint2*)(cb + (((wx * 8 + nt) * 4) * 32 + lane) * 8);
            bfr[0][nt][0] = v.x; bfr[0][nt][1] = v.y;
        }

        if (kc < 2) load_stage((kc + 2) % 3, kc + 2);

#pragma unroll
        for (int ks = 0; ks < 4; ks++) {
            const int cur = ks & 1;
            if (ks < 3) {
                const int nxt = cur ^ 1;
#pragma unroll
                for (int mt = 0; mt < 4; mt++) {
                    const uint4 v = *(const uint4*)(ca
                        + (((wy * 4 + mt) * 4 + ks + 1) * 32 + lane) * 16);
                    afr[nxt][mt][0] = v.x; afr[nxt][mt][1] = v.y;
                    afr[nxt][mt][2] = v.z; afr[nxt][mt][3] = v.w;
                }
#pragma unroll
                for (int nt = 0; nt < 8; nt++) {
                    const uint2 v = *(const uint2*)(cb
                        + (((wx * 8 + nt) * 4 + ks + 1) * 32 + lane) * 8);
                    bfr[nxt][nt][0] = v.x; bfr[nxt][nt][1] = v.y;
                }
            }
#pragma unroll
            for (int mt = 0; mt < 4; mt++)
#pragma unroll
                for (int nt = 0; nt < 8; nt++)
                    mma_f16(acc[mt][nt], afr[cur][mt], bfr[cur][nt]);
        }
    }

    // epilogue: stage fp16 tile in smem (row pad 132 half2), then coalesced store
    __syncthreads();
    __half2* st = (__half2*)gsm;
#pragma unroll
    for (int mt = 0; mt < 4; mt++) {
        const int r0 = wy * 64 + mt * 16 + gid;
#pragma unroll
        for (int nt = 0; nt < 8; nt++) {
            const int n2 = wx * 32 + nt * 4 + qid;
            st[r0 * 132 + n2]       = __floats2half2_rn(acc[mt][nt][0], acc[mt][nt][1]);
            st[(r0 + 8) * 132 + n2] = __floats2half2_rn(acc[mt][nt][2], acc[mt][nt][3]);
        }
    }
    __syncthreads();

    uint4* Z4 = (uint4*)g_Zh;
#pragma unroll
    for (int it = 0; it < 16; it++) {
        const int idx = it * 128 + tid;
        const int row = idx >> 4;
        const int ch  = idx & 15;
        const uint4 v = *(const uint4*)(gsm + row * 528 + ch * 16);
        Z4[((size_t)z * HWP + pb0 * 16 + row) * 32 + nb0 + ch] = v;
    }
}

// =============================================================================
// combine (prep fused): sampling meta from g_om inline, gather Z fp16,
// BN+ReLU+residual.
// =============================================================================
__global__ __launch_bounds__(256) void combine_kernel(
    const float* __restrict__ x, const float* __restrict__ b_conv,
    const float* __restrict__ gamma, const float* __restrict__ beta,
    const float* __restrict__ run_mean, const float* __restrict__ run_var,
    float* __restrict__ out)
{
    __shared__ int   sI[32][36];
    __shared__ float sWt[32][36];
    __shared__ float sA[256], sB[256];
    __shared__ float trans[256 * 33];

    const int b  = blockIdx.y;
    const int p0 = blockIdx.x * 32;
    const int tid = threadIdx.x;

    {
        const int o = tid;
        const float inv = rsqrtf(run_var[o] + EPSBN);
        const float a = inv * gamma[o];
        sA[o] = a;
        sB[o] = (b_conv[o] - run_mean[o]) * a + beta[o];
    }

    const float* omb = g_om + (size_t)b * 27 * HWP;
    for (int i = tid; i < 32 * 9; i += 256) {
        const int px = i & 31;
        const int k  = i >> 5;
        const int p  = p0 + px;

        const float dy = omb[(2 * k) * HWP + p];
        const float dx = omb[(2 * k + 1) * HWP + p];
        const float mv = omb[(18 + k) * HWP + p];
        const float m  = 1.f / (1.f + expf(-mv));

        const int h = p / WW, w = p - h * WW;
        const float py = (float)h + (float)(k / 3 - 1) + dy;
        const float px_ = (float)w + (float)(k % 3 - 1) + dx;
        const float y0f = floorf(py), x0f = floorf(px_);
        const float ly = py - y0f, lx = px_ - x0f;
        const int y0 = (int)y0f, x0 = (int)x0f;
        const int y1 = y0 + 1,   x1 = x0 + 1;

        const bool vy0 = (y0 >= 0) & (y0 < HH);
        const bool vy1 = (y1 >= 0) & (y1 < HH);
        const bool vx0 = (x0 >= 0) & (x0 < WW);
        const bool vx1 = (x1 >= 0) & (x1 < WW);
        const int y0c = min(max(y0, 0), HH - 1), y1c = min(max(y1, 0), HH - 1);
        const int x0c = min(max(x0, 0), WW - 1), x1c = min(max(x1, 0), WW - 1);

        int4 idx;
        idx.x = y0c * WW + x0c;
        idx.y = y0c * WW + x1c;
        idx.z = y1c * WW + x0c;
        idx.w = y1c * WW + x1c;
        float4 wt;
        wt.x = (1.f - ly) * (1.f - lx) * m * ((vy0 & vx0) ? 1.f : 0.f);
        wt.y = (1.f - ly) * lx         * m * ((vy0 & vx1) ? 1.f : 0.f);
        wt.z = ly * (1.f - lx)         * m * ((vy1 & vx0) ? 1.f : 0.f);
        wt.w = ly * lx                 * m * ((vy1 & vx1) ? 1.f : 0.f);

        *(int4*)&sI[px][k * 4]    = idx;
        *(float4*)&sWt[px][k * 4] = wt;
    }
    __syncthreads();

    const int og  = tid & 7;
    const int pxl = tid >> 3;

    float acc[4][8];
#pragma unroll
    for (int t = 0; t < 4; t++)
#pragma unroll
        for (int e = 0; e < 8; e++) acc[t][e] = 0.f;

    for (int k = 0; k < K9; k++) {
        const uint4* Zk = reinterpret_cast<const uint4*>(g_Zh)
                        + ((size_t)(b * K9 + k)) * HWP * 32;
#pragma unroll
        for (int j = 0; j < 4; j++) {
            const int   idx = sI[pxl][k * 4 + j];
            const float wj  = sWt[pxl][k * 4 + j];
            const uint4* src = Zk + (size_t)idx * 32 + og;
#pragma unroll
            for (int t = 0; t < 4; t++) {
                const uint4 u = src[t * 8];
                const float2 f0 = __half22float2(*reinterpret_cast<const __half2*>(&u.x));
                const float2 f1 = __half22float2(*reinterpret_cast<const __half2*>(&u.y));
                const float2 f2 = __half22float2(*reinterpret_cast<const __half2*>(&u.z));
                const float2 f3 = __half22float2(*reinterpret_cast<const __half2*>(&u.w));
                acc[t][0] += wj * f0.x; acc[t][1] += wj * f0.y;
                acc[t][2] += wj * f1.x; acc[t][3] += wj * f1.y;
                acc[t][4] += wj * f2.x; acc[t][5] += wj * f2.y;
                acc[t][6] += wj * f3.x; acc[t][7] += wj * f3.y;
            }
        }
    }

#pragma unroll
    for (int t = 0; t < 4; t++)
#pragma unroll
        for (int e = 0; e < 8; e++) {
            const int o = t * 64 + og * 8 + e;
            trans[o * 33 + pxl] = acc[t][e];
        }
    __syncthreads();

    const float* xb = x + ((size_t)b * CC) * HWP;
    float* ob = out + ((size_t)b * CC) * HWP;
    for (int pass = 0; pass < 32; pass++) {
        const int o   = (tid >> 5) + pass * 8;
        const int pxi = tid & 31;
        float v = trans[o * 33 + pxi];
        v = fmaxf(v * sA[o] + sB[o], 0.f);
        const size_t gi = (size_t)o * HWP + p0 + pxi;
        ob[gi] = xb[gi] + v;
    }
}

// =============================================================================
extern "C" void kernel_launch(void* const* d_in, const int* in_sizes, int n_in,
                              void* d_out, int out_size)
{
    const float* x        = (const float*)d_in[0];
    const float* w_off    = (const float*)d_in[1];
    const float* b_off    = (const float*)d_in[2];
    const float* w_conv   = (const float*)d_in[3];
    const float* b_conv   = (const float*)d_in[4];
    const float* gamma    = (const float*)d_in[5];
    const float* beta     = (const float*)d_in[6];
    const float* run_mean = (const float*)d_in[7];
    const float* run_var  = (const float*)d_in[8];
    float* out = (float*)d_out;

    // lazy one-time host-side resources (no device memory)
    static cudaStream_t s1 = nullptr;
    static cudaEvent_t eFork = nullptr, eW = nullptr, eA = nullptr, eO = nullptr;
    static bool attr_done = false;
    if (!s1) {
        cudaStreamCreateWithFlags(&s1, cudaStreamNonBlocking);
        cudaEventCreateWithFlags(&eFork, cudaEventDisableTiming);
        cudaEventCreateWithFlags(&eW,    cudaEventDisableTiming);
        cudaEventCreateWithFlags(&eA,    cudaEventDisableTiming);
        cudaEventCreateWithFlags(&eO,    cudaEventDisableTiming);
    }
    if (!attr_done) {
        cudaFuncSetAttribute(gemm_f16_kernel,
                             cudaFuncAttributeMaxDynamicSharedMemorySize, GEMM_SMEM);
        cudaFuncSetAttribute(offset_mma_cg_kernel,
                             cudaFuncAttributeMaxDynamicSharedMemorySize, OC_SMEM);
        attr_done = true;
    }

    cudaStream_t s0 = 0;   // origin (captured) stream

    // fork: s1 branches off s0
    cudaEventRecord(eFork, s0);
    cudaStreamWaitEvent(s1, eFork, 0);

    // s0: pack_a ; s1: pack_weights (independent)
    pack_a_fused_kernel<<<dim3(576, BB), 256, 0, s0>>>(x);
    pack_weights_kernel<<<(NWCONV + NWOFF + 255) / 256, 256, 0, s1>>>(w_conv, w_off);

    // cross dependencies: gemm (s0) needs pack_weights; offset (s1) needs pack_a
    cudaEventRecord(eW, s1);
    cudaEventRecord(eA, s0);
    cudaStreamWaitEvent(s0, eW, 0);
    cudaStreamWaitEvent(s1, eA, 0);

    // s0: gemm ; s1: offset path (cg-split partials -> sum)
    gemm_f16_kernel<<<dim3(HWP / 128, CC / 128, BB * K9), 128, GEMM_SMEM, s0>>>();
    offset_mma_cg_kernel<<<dim3(HH, BB, 4), 192, OC_SMEM, s1>>>();
    om_sum_kernel<<<(BB * 27 * HWP + 255) / 256, 256, 0, s1>>>(b_off);

    // join: combine needs both
    cudaEventRecord(eO, s1);
    cudaStreamWaitEvent(s0, eO, 0);
    combine_kernel<<<dim3(HWP / 32, BB), 256, 0, s0>>>(x, b_conv, gamma, beta,
                                                       run_mean, run_var, out);
}